// round 6
// baseline (speedup 1.0000x reference)
#include <cuda_runtime.h>
#include <cuda_bf16.h>
#include <stdint.h>
#include <math.h>

typedef __nv_bfloat16 bf16;

#define N_B    8
#define SEQ    512
#define DMODEL 4096
#define HEADS  8
#define HDIM   512
#define MTOT   4096
#define NBATCH 64
#define NELEM  (MTOT * DMODEL)

// GEMM tiling (mma.sync path, baseline PTX only)
#define BM   128
#define BN   256
#define BK   64                        // K elements per chunk (128B rows)
#define GT   256                       // 8 warps, warp tile 64x64
#define AH_OFF 0
#define AL_OFF 16384
#define BH_OFF 32768
#define BL_OFF 65536
#define STAGE_BYTES 98304              // Ah16K + Al16K + Bh32K + Bl32K
#define SMEM_REQ (2 * STAGE_BYTES)     // 192 KB, 2-stage double buffer

// ---------------------------------------------------------------------------
// Scratch (__device__ globals; allocation-free rule)
// ---------------------------------------------------------------------------
__device__ bf16 g_Xq_h[NELEM], g_Xq_l[NELEM];
__device__ bf16 g_Xk_h[NELEM], g_Xk_l[NELEM];
__device__ bf16 g_Xv_h[NELEM], g_Xv_l[NELEM];
__device__ bf16 g_Wq_h[NELEM], g_Wq_l[NELEM];
__device__ bf16 g_Wk_h[NELEM], g_Wk_l[NELEM];
__device__ bf16 g_Wv_h[NELEM], g_Wv_l[NELEM];
__device__ bf16 g_Wo_h[NELEM], g_Wo_l[NELEM];
__device__ bf16 g_Qh[NELEM], g_Ql[NELEM];
__device__ bf16 g_Kh[NELEM], g_Kl[NELEM];
__device__ bf16 g_Yh[NELEM], g_Yl[NELEM];
__device__ float g_V[NELEM];
__device__ float g_S[NELEM];

// ---------------------------------------------------------------------------
__device__ __forceinline__ uint32_t smem_u32(const void* p) {
    uint32_t a;
    asm("{ .reg .u64 t; cvta.to.shared.u64 t, %1; cvt.u32.u64 %0, t; }"
        : "=r"(a) : "l"(p));
    return a;
}
__device__ __forceinline__ void cp16(uint32_t dst, const void* src) {
    asm volatile("cp.async.cg.shared.global [%0], [%1], 16;"
                 :: "r"(dst), "l"(src) : "memory");
}
#define CP_COMMIT() asm volatile("cp.async.commit_group;" ::: "memory")
#define CP_WAIT(n)  asm volatile("cp.async.wait_group %0;" :: "n"(n) : "memory")

__device__ __forceinline__ void ldsm4(uint32_t& r0, uint32_t& r1,
                                      uint32_t& r2, uint32_t& r3, uint32_t a) {
    asm volatile("ldmatrix.sync.aligned.m8n8.x4.shared.b16 {%0,%1,%2,%3}, [%4];"
                 : "=r"(r0), "=r"(r1), "=r"(r2), "=r"(r3) : "r"(a));
}
__device__ __forceinline__ void mma16816(float* c, const uint32_t* a,
                                         const uint32_t* b) {
    asm volatile(
        "mma.sync.aligned.m16n8k16.row.col.f32.bf16.bf16.f32 "
        "{%0,%1,%2,%3}, {%4,%5,%6,%7}, {%8,%9}, {%0,%1,%2,%3};"
        : "+f"(c[0]), "+f"(c[1]), "+f"(c[2]), "+f"(c[3])
        : "r"(a[0]), "r"(a[1]), "r"(a[2]), "r"(a[3]), "r"(b[0]), "r"(b[1]));
}

// ---------------------------------------------------------------------------
// bf16x3 NT GEMM, pass-interleaved: per k-chunk load Ah,Al,Bh,Bl once, then
// acc += Ah*Bh + Ah*Bl + Al*Bh  (Al*Bl dropped; ~2^-18 relative)
// A: M x Kp row-major, B: Nn x Kp row-major, batched via blockIdx.z.
// ---------------------------------------------------------------------------
__global__ void __launch_bounds__(GT)
gemm_bf16x3(const bf16* __restrict__ Ah, const bf16* __restrict__ Al,
            const bf16* __restrict__ Bh, const bf16* __restrict__ Bl,
            float* __restrict__ Cf, bf16* __restrict__ Chi, bf16* __restrict__ Clo,
            const float* __restrict__ bias, float scale,
            int Kp, int Nn,
            long long sA, long long sB, long long sC)
{
    extern __shared__ char smem[];
    const uint32_t SB = smem_u32(smem);

    const int tid  = threadIdx.x;
    const int lane = tid & 31;
    const int wid  = tid >> 5;
    const int wm   = wid >> 2;            // 0..1 -> 64-row slab
    const int wn   = wid & 3;             // 0..3 -> 64-col slab
    const long long z = blockIdx.z;
    const bf16* Ah_ = Ah + z * sA;
    const bf16* Al_ = Al + z * sA;
    const bf16* Bh_ = Bh + z * sB;
    const bf16* Bl_ = Bl + z * sB;
    const int bm = blockIdx.y * BM;
    const int bn = blockIdx.x * BN;
    const int NS = Kp / BK;

    // ---- per-lane ldmatrix address bases (within a stage slot) ----
    const int grp = lane >> 3, lr = lane & 7;
    uint32_t a_rowoff[4], a_x7[4];
    #pragma unroll
    for (int mt = 0; mt < 4; mt++) {
        int r = wm * 64 + mt * 16 + lr + (grp & 1) * 8;
        a_rowoff[mt] = (uint32_t)r * 128;
        a_x7[mt] = (uint32_t)(r & 7);
    }
    const uint32_t a_cb = (uint32_t)(grp >> 1);
    uint32_t b_rowoff[4], b_x7[4];
    #pragma unroll
    for (int h = 0; h < 4; h++) {
        int r = wn * 64 + h * 16 + lr + ((grp >> 1) & 1) * 8;
        b_rowoff[h] = (uint32_t)r * 128;
        b_x7[h] = (uint32_t)(r & 7);
    }
    const uint32_t b_cb = (uint32_t)(grp & 1);

    float acc[4][8][4];
    #pragma unroll
    for (int i = 0; i < 4; i++)
        #pragma unroll
        for (int j = 0; j < 8; j++)
            #pragma unroll
            for (int k = 0; k < 4; k++) acc[i][j][k] = 0.f;

    auto load_stage = [&](int slot, int kk) {
        const uint32_t base = SB + slot * STAGE_BYTES;
        #pragma unroll
        for (int i = 0; i < 4; i++) {             // A tiles: 1024 chunks each
            int id = tid + i * GT, r = id >> 3, c = id & 7;
            uint32_t off = r * 128 + ((c ^ (r & 7)) * 16);
            const size_t g = (size_t)(bm + r) * Kp + kk + c * 8;
            cp16(base + AH_OFF + off, Ah_ + g);
            cp16(base + AL_OFF + off, Al_ + g);
        }
        #pragma unroll
        for (int i = 0; i < 8; i++) {             // B tiles: 2048 chunks each
            int id = tid + i * GT, r = id >> 3, c = id & 7;
            uint32_t off = r * 128 + ((c ^ (r & 7)) * 16);
            const size_t g = (size_t)(bn + r) * Kp + kk + c * 8;
            cp16(base + BH_OFF + off, Bh_ + g);
            cp16(base + BL_OFF + off, Bl_ + g);
        }
    };

    load_stage(0, 0);
    CP_COMMIT();

    for (int ks = 0; ks < NS; ks++) {
        CP_WAIT(0);
        __syncthreads();

        if (ks + 1 < NS) load_stage((ks + 1) & 1, (ks + 1) * BK);
        CP_COMMIT();

        const uint32_t base = SB + (ks & 1) * STAGE_BYTES;
        #pragma unroll
        for (int kst = 0; kst < 4; kst++) {
            uint32_t ah[4][4], al[4][4], bh[4][4], bl[4][4];
            #pragma unroll
            for (int mt = 0; mt < 4; mt++) {
                const uint32_t co = (((kst * 2 + a_cb) ^ a_x7[mt]) * 16) + a_rowoff[mt];
                ldsm4(ah[mt][0], ah[mt][1], ah[mt][2], ah[mt][3], base + AH_OFF + co);
                ldsm4(al[mt][0], al[mt][1], al[mt][2], al[mt][3], base + AL_OFF + co);
            }
            #pragma unroll
            for (int h = 0; h < 4; h++) {
                const uint32_t co = (((kst * 2 + b_cb) ^ b_x7[h]) * 16) + b_rowoff[h];
                ldsm4(bh[h][0], bh[h][1], bh[h][2], bh[h][3], base + BH_OFF + co);
                ldsm4(bl[h][0], bl[h][1], bl[h][2], bl[h][3], base + BL_OFF + co);
            }
            #pragma unroll
            for (int mt = 0; mt < 4; mt++)
                #pragma unroll
                for (int nt = 0; nt < 8; nt++) {
                    mma16816(acc[mt][nt], ah[mt], &bh[nt >> 1][(nt & 1) * 2]);
                    mma16816(acc[mt][nt], ah[mt], &bl[nt >> 1][(nt & 1) * 2]);
                    mma16816(acc[mt][nt], al[mt], &bh[nt >> 1][(nt & 1) * 2]);
                }
        }
    }

    // ------------------------- epilogue -------------------------
    const int qr = lane >> 2, qc = (lane & 3) * 2;
    #pragma unroll
    for (int mt = 0; mt < 4; mt++) {
        #pragma unroll
        for (int half = 0; half < 2; half++) {
            const size_t row = (size_t)(bm + wm * 64 + mt * 16 + qr + half * 8);
            #pragma unroll
            for (int nt = 0; nt < 8; nt++) {
                const int col = bn + wn * 64 + nt * 8 + qc;
                float v0 = acc[mt][nt][half * 2 + 0] * scale;
                float v1 = acc[mt][nt][half * 2 + 1] * scale;
                if (bias) { v0 += bias[col]; v1 += bias[col + 1]; }
                if (Cf) {
                    float2 o; o.x = v0; o.y = v1;
                    *reinterpret_cast<float2*>(Cf + z * sC + row * Nn + col) = o;
                } else {
                    bf16 h0 = __float2bfloat16(v0);
                    bf16 h1 = __float2bfloat16(v1);
                    __nv_bfloat162 hh; hh.x = h0; hh.y = h1;
                    __nv_bfloat162 ll;
                    ll.x = __float2bfloat16(v0 - __bfloat162float(h0));
                    ll.y = __float2bfloat16(v1 - __bfloat162float(h1));
                    *reinterpret_cast<__nv_bfloat162*>(Chi + z * sC + row * Nn + col) = hh;
                    *reinterpret_cast<__nv_bfloat162*>(Clo + z * sC + row * Nn + col) = ll;
                }
            }
        }
    }
}

// ---------------------------------------------------------------------------
// fp32 -> bf16 hi/lo split, batched (up to 4 arrays per launch via blockIdx.y)
// ---------------------------------------------------------------------------
struct SplitArgs {
    const float4* src[4];
    __nv_bfloat162* hi[4];
    __nv_bfloat162* lo[4];
};

__global__ void __launch_bounds__(256) split_multi(SplitArgs args, int n4)
{
    int a = blockIdx.y;
    const float4* x = args.src[a];
    __nv_bfloat162* hi = args.hi[a];
    __nv_bfloat162* lo = args.lo[a];
    int i = blockIdx.x * 256 + threadIdx.x;
    if (i >= n4) return;
    float4 v = x[i];
    bf16 h0 = __float2bfloat16(v.x), h1 = __float2bfloat16(v.y);
    bf16 h2 = __float2bfloat16(v.z), h3 = __float2bfloat16(v.w);
    __nv_bfloat162 ha; ha.x = h0; ha.y = h1;
    __nv_bfloat162 hb; hb.x = h2; hb.y = h3;
    __nv_bfloat162 la, lb;
    la.x = __float2bfloat16(v.x - __bfloat162float(h0));
    la.y = __float2bfloat16(v.y - __bfloat162float(h1));
    lb.x = __float2bfloat16(v.z - __bfloat162float(h2));
    lb.y = __float2bfloat16(v.w - __bfloat162float(h3));
    hi[2 * i] = ha; hi[2 * i + 1] = hb;
    lo[2 * i] = la; lo[2 * i + 1] = lb;
}

// ---------------------------------------------------------------------------
// Column softmax (axis s) * V, head-interleave scatter, bf16 hi/lo split out
// ---------------------------------------------------------------------------
__global__ void __launch_bounds__(256) softmax_mul_scatter(
    const float* __restrict__ S, const float* __restrict__ V,
    bf16* __restrict__ Yh, bf16* __restrict__ Yl)
{
    int idx = blockIdx.x * blockDim.x + threadIdx.x;   // 0 .. 64*512-1
    int b = idx >> 9, t = idx & 511;
    int n = b >> 3, h = b & 7;

    const float* col  = S + (size_t)b * SEQ * SEQ + t;
    const float* vcol = V + (size_t)b * SEQ * SEQ + t;
    size_t ybase = (size_t)n * SEQ * DMODEL + h * HDIM + t;

    float m = -1e30f, l = 0.f;
    for (int s = 0; s < SEQ; s++) {
        float x = col[(size_t)s * SEQ];
        float nm = fmaxf(m, x);
        l = l * __expf(m - nm) + __expf(x - nm);
        m = nm;
    }
    float inv = 1.f / l;
    for (int s = 0; s < SEQ; s++) {
        float x  = col[(size_t)s * SEQ];
        float yv = __expf(x - m) * inv * vcol[(size_t)s * SEQ];
        bf16 hh = __float2bfloat16(yv);
        size_t off = ybase + (size_t)s * DMODEL;
        Yh[off] = hh;
        Yl[off] = __float2bfloat16(yv - __bfloat162float(hh));
    }
}

// ---------------------------------------------------------------------------
extern "C" void kernel_launch(void* const* d_in, const int* in_sizes, int n_in,
                              void* d_out, int out_size)
{
    const float* query = (const float*)d_in[0];
    const float* key   = (const float*)d_in[1];
    const float* value = (const float*)d_in[2];
    const float* Wq    = (const float*)d_in[3];
    const float* bq    = (const float*)d_in[4];
    const float* Wk    = (const float*)d_in[5];
    const float* bk    = (const float*)d_in[6];
    const float* Wv    = (const float*)d_in[7];
    const float* bv    = (const float*)d_in[8];
    const float* Wo    = (const float*)d_in[9];
    const float* bo    = (const float*)d_in[10];
    float* out = (float*)d_out;

    cudaFuncSetAttribute(gemm_bf16x3,
                         cudaFuncAttributeMaxDynamicSharedMemorySize, SMEM_REQ);

    bf16 *Xq_h, *Xq_l, *Xk_h, *Xk_l, *Xv_h, *Xv_l;
    bf16 *Wq_h, *Wq_l, *Wk_h, *Wk_l, *Wv_h, *Wv_l, *Wo_h, *Wo_l;
    bf16 *Qh, *Ql, *Kh, *Kl, *Yh, *Yl;
    float *Vf, *Sf;
    cudaGetSymbolAddress((void**)&Xq_h, g_Xq_h); cudaGetSymbolAddress((void**)&Xq_l, g_Xq_l);
    cudaGetSymbolAddress((void**)&Xk_h, g_Xk_h); cudaGetSymbolAddress((void**)&Xk_l, g_Xk_l);
    cudaGetSymbolAddress((void**)&Xv_h, g_Xv_h); cudaGetSymbolAddress((void**)&Xv_l, g_Xv_l);
    cudaGetSymbolAddress((void**)&Wq_h, g_Wq_h); cudaGetSymbolAddress((void**)&Wq_l, g_Wq_l);
    cudaGetSymbolAddress((void**)&Wk_h, g_Wk_h); cudaGetSymbolAddress((void**)&Wk_l, g_Wk_l);
    cudaGetSymbolAddress((void**)&Wv_h, g_Wv_h); cudaGetSymbolAddress((void**)&Wv_l, g_Wv_l);
    cudaGetSymbolAddress((void**)&Wo_h, g_Wo_h); cudaGetSymbolAddress((void**)&Wo_l, g_Wo_l);
    cudaGetSymbolAddress((void**)&Qh, g_Qh); cudaGetSymbolAddress((void**)&Ql, g_Ql);
    cudaGetSymbolAddress((void**)&Kh, g_Kh); cudaGetSymbolAddress((void**)&Kl, g_Kl);
    cudaGetSymbolAddress((void**)&Yh, g_Yh); cudaGetSymbolAddress((void**)&Yl, g_Yl);
    cudaGetSymbolAddress((void**)&Vf, g_V);  cudaGetSymbolAddress((void**)&Sf, g_S);

    const int n4 = NELEM / 4;
    const int sg = (n4 + 255) / 256;

    // L1: split query,key,value,Wq   L2: split Wk,Wv,Wo
    {
        SplitArgs a1;
        a1.src[0] = (const float4*)query; a1.hi[0] = (__nv_bfloat162*)Xq_h; a1.lo[0] = (__nv_bfloat162*)Xq_l;
        a1.src[1] = (const float4*)key;   a1.hi[1] = (__nv_bfloat162*)Xk_h; a1.lo[1] = (__nv_bfloat162*)Xk_l;
        a1.src[2] = (const float4*)value; a1.hi[2] = (__nv_bfloat162*)Xv_h; a1.lo[2] = (__nv_bfloat162*)Xv_l;
        a1.src[3] = (const float4*)Wq;    a1.hi[3] = (__nv_bfloat162*)Wq_h; a1.lo[3] = (__nv_bfloat162*)Wq_l;
        split_multi<<<dim3(sg, 4), 256>>>(a1, n4);
        SplitArgs a2;
        a2.src[0] = (const float4*)Wk;    a2.hi[0] = (__nv_bfloat162*)Wk_h; a2.lo[0] = (__nv_bfloat162*)Wk_l;
        a2.src[1] = (const float4*)Wv;    a2.hi[1] = (__nv_bfloat162*)Wv_h; a2.lo[1] = (__nv_bfloat162*)Wv_l;
        a2.src[2] = (const float4*)Wo;    a2.hi[2] = (__nv_bfloat162*)Wo_h; a2.lo[2] = (__nv_bfloat162*)Wo_l;
        a2.src[3] = (const float4*)Wq;    a2.hi[3] = (__nv_bfloat162*)Wq_h; a2.lo[3] = (__nv_bfloat162*)Wq_l; // unused lane guard
        split_multi<<<dim3(sg, 3), 256>>>(a2, n4);
    }

    dim3 blk(GT);
    dim3 gP(DMODEL / BN, MTOT / BM, 1);            // 16 x 32

    // L3: Q   L4: K   L5: scores   L6: V (<- ncu capture slot)   L7: softmax   L8: out
    gemm_bf16x3<<<gP, blk, SMEM_REQ>>>(Xq_h, Xq_l, Wq_h, Wq_l,
        nullptr, Qh, Ql, bq, 1.f, DMODEL, DMODEL, 0, 0, 0);
    gemm_bf16x3<<<gP, blk, SMEM_REQ>>>(Xk_h, Xk_l, Wk_h, Wk_l,
        nullptr, Kh, Kl, bk, 1.f, DMODEL, DMODEL, 0, 0, 0);
    {
        dim3 gS(SEQ / BN, SEQ / BM, NBATCH);       // 2 x 4 x 64
        long long sbz = (long long)SEQ * SEQ;
        gemm_bf16x3<<<gS, blk, SMEM_REQ>>>(Qh, Ql, Kh, Kl,
            Sf, nullptr, nullptr, nullptr, rsqrtf((float)HDIM),
            HDIM, SEQ, sbz, sbz, sbz);
    }
    gemm_bf16x3<<<gP, blk, SMEM_REQ>>>(Xv_h, Xv_l, Wv_h, Wv_l,
        Vf, nullptr, nullptr, bv, 1.f, DMODEL, DMODEL, 0, 0, 0);

    softmax_mul_scatter<<<(NBATCH * SEQ) / 256, 256>>>(Sf, Vf, Yh, Yl);

    gemm_bf16x3<<<gP, blk, SMEM_REQ>>>(Yh, Yl, Wo_h, Wo_l,
        out, nullptr, nullptr, bo, 1.f, DMODEL, DMODEL, 0, 0, 0);
}

// round 8
// speedup vs baseline: 1.0745x; 1.0745x over previous
#include <cuda_runtime.h>
#include <cuda_bf16.h>
#include <stdint.h>
#include <math.h>

typedef __nv_bfloat16 bf16;

#define N_B    8
#define SEQ    512
#define DMODEL 4096
#define HEADS  8
#define HDIM   512
#define MTOT   4096
#define NBATCH 64
#define NELEM  (MTOT * DMODEL)

// GEMM tiling (mma.sync path, baseline PTX only)
#define BM   128
#define BN   64
#define BK   64                        // K elements per chunk (128B rows)
#define GT   256                       // 8 warps, warp grid 4(m) x 2(n), tile 32x32
#define AH_OFF 0
#define AL_OFF 16384
#define BH_OFF 32768
#define BL_OFF 40960
#define STAGE_BYTES 49152              // Ah16K + Al16K + Bh8K + Bl8K
#define SMEM_REQ (2 * STAGE_BYTES)     // 96 KB/CTA, 2-stage; 2 CTAs/SM = 192 KB

// ---------------------------------------------------------------------------
// Scratch (__device__ globals; allocation-free rule)
// ---------------------------------------------------------------------------
__device__ bf16 g_Xq_h[NELEM], g_Xq_l[NELEM];
__device__ bf16 g_Xk_h[NELEM], g_Xk_l[NELEM];
__device__ bf16 g_Xv_h[NELEM], g_Xv_l[NELEM];
__device__ bf16 g_Wq_h[NELEM], g_Wq_l[NELEM];
__device__ bf16 g_Wk_h[NELEM], g_Wk_l[NELEM];
__device__ bf16 g_Wv_h[NELEM], g_Wv_l[NELEM];
__device__ bf16 g_Wo_h[NELEM], g_Wo_l[NELEM];
__device__ bf16 g_Qh[NELEM], g_Ql[NELEM];
__device__ bf16 g_Kh[NELEM], g_Kl[NELEM];
__device__ bf16 g_Yh[NELEM], g_Yl[NELEM];
__device__ float g_V[NELEM];
__device__ float g_S[NELEM];

// ---------------------------------------------------------------------------
__device__ __forceinline__ uint32_t smem_u32(const void* p) {
    uint32_t a;
    asm("{ .reg .u64 t; cvta.to.shared.u64 t, %1; cvt.u32.u64 %0, t; }"
        : "=r"(a) : "l"(p));
    return a;
}
__device__ __forceinline__ void cp16(uint32_t dst, const void* src) {
    asm volatile("cp.async.cg.shared.global [%0], [%1], 16;"
                 :: "r"(dst), "l"(src) : "memory");
}
#define CP_COMMIT() asm volatile("cp.async.commit_group;" ::: "memory")
#define CP_WAIT(n)  asm volatile("cp.async.wait_group %0;" :: "n"(n) : "memory")

__device__ __forceinline__ void ldsm4(uint32_t& r0, uint32_t& r1,
                                      uint32_t& r2, uint32_t& r3, uint32_t a) {
    asm volatile("ldmatrix.sync.aligned.m8n8.x4.shared.b16 {%0,%1,%2,%3}, [%4];"
                 : "=r"(r0), "=r"(r1), "=r"(r2), "=r"(r3) : "r"(a));
}
__device__ __forceinline__ void mma16816(float* c, const uint32_t* a,
                                         const uint32_t* b) {
    asm volatile(
        "mma.sync.aligned.m16n8k16.row.col.f32.bf16.bf16.f32 "
        "{%0,%1,%2,%3}, {%4,%5,%6,%7}, {%8,%9}, {%0,%1,%2,%3};"
        : "+f"(c[0]), "+f"(c[1]), "+f"(c[2]), "+f"(c[3])
        : "r"(a[0]), "r"(a[1]), "r"(a[2]), "r"(a[3]), "r"(b[0]), "r"(b[1]));
}

// ---------------------------------------------------------------------------
// bf16x3 NT GEMM, pass-interleaved: per k-chunk load Ah,Al,Bh,Bl once, then
// acc += Ah*Bh + Ah*Bl + Al*Bh  (Al*Bl dropped; ~2^-18 relative)
// A: M x Kp row-major, B: Nn x Kp row-major, batched via blockIdx.z.
// Sized for 2 CTAs/SM (regs <= 128, smem 96 KB).
// ---------------------------------------------------------------------------
__global__ void __launch_bounds__(GT, 2)
gemm_bf16x3(const bf16* __restrict__ Ah, const bf16* __restrict__ Al,
            const bf16* __restrict__ Bh, const bf16* __restrict__ Bl,
            float* __restrict__ Cf, bf16* __restrict__ Chi, bf16* __restrict__ Clo,
            const float* __restrict__ bias, float scale,
            int Kp, int Nn,
            long long sA, long long sB, long long sC)
{
    extern __shared__ char smem[];
    const uint32_t SB = smem_u32(smem);

    const int tid  = threadIdx.x;
    const int lane = tid & 31;
    const int wid  = tid >> 5;
    const int wm   = wid >> 1;            // 0..3 -> 32-row slab
    const int wn   = wid & 1;             // 0..1 -> 32-col slab
    const long long z = blockIdx.z;
    const bf16* Ah_ = Ah + z * sA;
    const bf16* Al_ = Al + z * sA;
    const bf16* Bh_ = Bh + z * sB;
    const bf16* Bl_ = Bl + z * sB;
    const int bm = blockIdx.y * BM;
    const int bn = blockIdx.x * BN;
    const int NS = Kp / BK;

    // ---- per-lane ldmatrix address bases (within a stage slot) ----
    const int grp = lane >> 3, lr = lane & 7;
    uint32_t a_rowoff[2], a_x7[2];
    #pragma unroll
    for (int mt = 0; mt < 2; mt++) {
        int r = wm * 32 + mt * 16 + lr + (grp & 1) * 8;
        a_rowoff[mt] = (uint32_t)r * 128;
        a_x7[mt] = (uint32_t)(r & 7);
    }
    const uint32_t a_cb = (uint32_t)(grp >> 1);
    uint32_t b_rowoff[2], b_x7[2];
    #pragma unroll
    for (int h = 0; h < 2; h++) {
        int r = wn * 32 + h * 16 + lr + ((grp >> 1) & 1) * 8;
        b_rowoff[h] = (uint32_t)r * 128;
        b_x7[h] = (uint32_t)(r & 7);
    }
    const uint32_t b_cb = (uint32_t)(grp & 1);

    float acc[2][4][4];
    #pragma unroll
    for (int i = 0; i < 2; i++)
        #pragma unroll
        for (int j = 0; j < 4; j++)
            #pragma unroll
            for (int k = 0; k < 4; k++) acc[i][j][k] = 0.f;

    auto load_stage = [&](int slot, int kk) {
        const uint32_t base = SB + slot * STAGE_BYTES;
        #pragma unroll
        for (int i = 0; i < 4; i++) {             // A tiles: 1024 chunks each
            int id = tid + i * GT, r = id >> 3, c = id & 7;
            uint32_t off = r * 128 + ((c ^ (r & 7)) * 16);
            const size_t g = (size_t)(bm + r) * Kp + kk + c * 8;
            cp16(base + AH_OFF + off, Ah_ + g);
            cp16(base + AL_OFF + off, Al_ + g);
        }
        #pragma unroll
        for (int i = 0; i < 2; i++) {             // B tiles: 512 chunks each
            int id = tid + i * GT, r = id >> 3, c = id & 7;
            uint32_t off = r * 128 + ((c ^ (r & 7)) * 16);
            const size_t g = (size_t)(bn + r) * Kp + kk + c * 8;
            cp16(base + BH_OFF + off, Bh_ + g);
            cp16(base + BL_OFF + off, Bl_ + g);
        }
    };

    load_stage(0, 0);
    CP_COMMIT();

    for (int ks = 0; ks < NS; ks++) {
        CP_WAIT(0);
        __syncthreads();

        if (ks + 1 < NS) load_stage((ks + 1) & 1, (ks + 1) * BK);
        CP_COMMIT();

        const uint32_t base = SB + (ks & 1) * STAGE_BYTES;
        #pragma unroll
        for (int kst = 0; kst < 4; kst++) {
            uint32_t ah[2][4], al[2][4], bh[2][4], bl[2][4];
            #pragma unroll
            for (int mt = 0; mt < 2; mt++) {
                const uint32_t co = (((kst * 2 + a_cb) ^ a_x7[mt]) * 16) + a_rowoff[mt];
                ldsm4(ah[mt][0], ah[mt][1], ah[mt][2], ah[mt][3], base + AH_OFF + co);
                ldsm4(al[mt][0], al[mt][1], al[mt][2], al[mt][3], base + AL_OFF + co);
            }
            #pragma unroll
            for (int h = 0; h < 2; h++) {
                const uint32_t co = (((kst * 2 + b_cb) ^ b_x7[h]) * 16) + b_rowoff[h];
                ldsm4(bh[h][0], bh[h][1], bh[h][2], bh[h][3], base + BH_OFF + co);
                ldsm4(bl[h][0], bl[h][1], bl[h][2], bl[h][3], base + BL_OFF + co);
            }
            // pass-ordered: consecutive MMAs never share an accumulator
            #pragma unroll
            for (int mt = 0; mt < 2; mt++)
                #pragma unroll
                for (int nt = 0; nt < 4; nt++)
                    mma16816(acc[mt][nt], ah[mt], &bh[nt >> 1][(nt & 1) * 2]);
            #pragma unroll
            for (int mt = 0; mt < 2; mt++)
                #pragma unroll
                for (int nt = 0; nt < 4; nt++)
                    mma16816(acc[mt][nt], ah[mt], &bl[nt >> 1][(nt & 1) * 2]);
            #pragma unroll
            for (int mt = 0; mt < 2; mt++)
                #pragma unroll
                for (int nt = 0; nt < 4; nt++)
                    mma16816(acc[mt][nt], al[mt], &bh[nt >> 1][(nt & 1) * 2]);
        }
    }

    // ------------------------- epilogue -------------------------
    const int qr = lane >> 2, qc = (lane & 3) * 2;
    #pragma unroll
    for (int mt = 0; mt < 2; mt++) {
        #pragma unroll
        for (int half = 0; half < 2; half++) {
            const size_t row = (size_t)(bm + wm * 32 + mt * 16 + qr + half * 8);
            #pragma unroll
            for (int nt = 0; nt < 4; nt++) {
                const int col = bn + wn * 32 + nt * 8 + qc;
                float v0 = acc[mt][nt][half * 2 + 0] * scale;
                float v1 = acc[mt][nt][half * 2 + 1] * scale;
                if (bias) { v0 += bias[col]; v1 += bias[col + 1]; }
                if (Cf) {
                    float2 o; o.x = v0; o.y = v1;
                    *reinterpret_cast<float2*>(Cf + z * sC + row * Nn + col) = o;
                } else {
                    bf16 h0 = __float2bfloat16(v0);
                    bf16 h1 = __float2bfloat16(v1);
                    __nv_bfloat162 hh; hh.x = h0; hh.y = h1;
                    __nv_bfloat162 ll;
                    ll.x = __float2bfloat16(v0 - __bfloat162float(h0));
                    ll.y = __float2bfloat16(v1 - __bfloat162float(h1));
                    *reinterpret_cast<__nv_bfloat162*>(Chi + z * sC + row * Nn + col) = hh;
                    *reinterpret_cast<__nv_bfloat162*>(Clo + z * sC + row * Nn + col) = ll;
                }
            }
        }
    }
}

// ---------------------------------------------------------------------------
// fp32 -> bf16 hi/lo split, batched (up to 4 arrays per launch via blockIdx.y)
// ---------------------------------------------------------------------------
struct SplitArgs {
    const float4* src[4];
    __nv_bfloat162* hi[4];
    __nv_bfloat162* lo[4];
};

__global__ void __launch_bounds__(256) split_multi(SplitArgs args, int n4)
{
    int a = blockIdx.y;
    const float4* x = args.src[a];
    __nv_bfloat162* hi = args.hi[a];
    __nv_bfloat162* lo = args.lo[a];
    int i = blockIdx.x * 256 + threadIdx.x;
    if (i >= n4) return;
    float4 v = x[i];
    bf16 h0 = __float2bfloat16(v.x), h1 = __float2bfloat16(v.y);
    bf16 h2 = __float2bfloat16(v.z), h3 = __float2bfloat16(v.w);
    __nv_bfloat162 ha; ha.x = h0; ha.y = h1;
    __nv_bfloat162 hb; hb.x = h2; hb.y = h3;
    __nv_bfloat162 la, lb;
    la.x = __float2bfloat16(v.x - __bfloat162float(h0));
    la.y = __float2bfloat16(v.y - __bfloat162float(h1));
    lb.x = __float2bfloat16(v.z - __bfloat162float(h2));
    lb.y = __float2bfloat16(v.w - __bfloat162float(h3));
    hi[2 * i] = ha; hi[2 * i + 1] = hb;
    lo[2 * i] = la; lo[2 * i + 1] = lb;
}

// ---------------------------------------------------------------------------
// Column softmax (axis s) * V, head-interleave scatter, bf16 hi/lo split out
// ---------------------------------------------------------------------------
__global__ void __launch_bounds__(256) softmax_mul_scatter(
    const float* __restrict__ S, const float* __restrict__ V,
    bf16* __restrict__ Yh, bf16* __restrict__ Yl)
{
    int idx = blockIdx.x * blockDim.x + threadIdx.x;   // 0 .. 64*512-1
    int b = idx >> 9, t = idx & 511;
    int n = b >> 3, h = b & 7;

    const float* col  = S + (size_t)b * SEQ * SEQ + t;
    const float* vcol = V + (size_t)b * SEQ * SEQ + t;
    size_t ybase = (size_t)n * SEQ * DMODEL + h * HDIM + t;

    float m = -1e30f, l = 0.f;
    for (int s = 0; s < SEQ; s++) {
        float x = col[(size_t)s * SEQ];
        float nm = fmaxf(m, x);
        l = l * __expf(m - nm) + __expf(x - nm);
        m = nm;
    }
    float inv = 1.f / l;
    for (int s = 0; s < SEQ; s++) {
        float x  = col[(size_t)s * SEQ];
        float yv = __expf(x - m) * inv * vcol[(size_t)s * SEQ];
        bf16 hh = __float2bfloat16(yv);
        size_t off = ybase + (size_t)s * DMODEL;
        Yh[off] = hh;
        Yl[off] = __float2bfloat16(yv - __bfloat162float(hh));
    }
}

// ---------------------------------------------------------------------------
extern "C" void kernel_launch(void* const* d_in, const int* in_sizes, int n_in,
                              void* d_out, int out_size)
{
    const float* query = (const float*)d_in[0];
    const float* key   = (const float*)d_in[1];
    const float* value = (const float*)d_in[2];
    const float* Wq    = (const float*)d_in[3];
    const float* bq    = (const float*)d_in[4];
    const float* Wk    = (const float*)d_in[5];
    const float* bk    = (const float*)d_in[6];
    const float* Wv    = (const float*)d_in[7];
    const float* bv    = (const float*)d_in[8];
    const float* Wo    = (const float*)d_in[9];
    const float* bo    = (const float*)d_in[10];
    float* out = (float*)d_out;

    cudaFuncSetAttribute(gemm_bf16x3,
                         cudaFuncAttributeMaxDynamicSharedMemorySize, SMEM_REQ);

    bf16 *Xq_h, *Xq_l, *Xk_h, *Xk_l, *Xv_h, *Xv_l;
    bf16 *Wq_h, *Wq_l, *Wk_h, *Wk_l, *Wv_h, *Wv_l, *Wo_h, *Wo_l;
    bf16 *Qh, *Ql, *Kh, *Kl, *Yh, *Yl;
    float *Vf, *Sf;
    cudaGetSymbolAddress((void**)&Xq_h, g_Xq_h); cudaGetSymbolAddress((void**)&Xq_l, g_Xq_l);
    cudaGetSymbolAddress((void**)&Xk_h, g_Xk_h); cudaGetSymbolAddress((void**)&Xk_l, g_Xk_l);
    cudaGetSymbolAddress((void**)&Xv_h, g_Xv_h); cudaGetSymbolAddress((void**)&Xv_l, g_Xv_l);
    cudaGetSymbolAddress((void**)&Wq_h, g_Wq_h); cudaGetSymbolAddress((void**)&Wq_l, g_Wq_l);
    cudaGetSymbolAddress((void**)&Wk_h, g_Wk_h); cudaGetSymbolAddress((void**)&Wk_l, g_Wk_l);
    cudaGetSymbolAddress((void**)&Wv_h, g_Wv_h); cudaGetSymbolAddress((void**)&Wv_l, g_Wv_l);
    cudaGetSymbolAddress((void**)&Wo_h, g_Wo_h); cudaGetSymbolAddress((void**)&Wo_l, g_Wo_l);
    cudaGetSymbolAddress((void**)&Qh, g_Qh); cudaGetSymbolAddress((void**)&Ql, g_Ql);
    cudaGetSymbolAddress((void**)&Kh, g_Kh); cudaGetSymbolAddress((void**)&Kl, g_Kl);
    cudaGetSymbolAddress((void**)&Yh, g_Yh); cudaGetSymbolAddress((void**)&Yl, g_Yl);
    cudaGetSymbolAddress((void**)&Vf, g_V);  cudaGetSymbolAddress((void**)&Sf, g_S);

    const int n4 = NELEM / 4;
    const int sg = (n4 + 255) / 256;

    // L1: split query,key,value,Wq   L2: split Wk,Wv,Wo
    {
        SplitArgs a1;
        a1.src[0] = (const float4*)query; a1.hi[0] = (__nv_bfloat162*)Xq_h; a1.lo[0] = (__nv_bfloat162*)Xq_l;
        a1.src[1] = (const float4*)key;   a1.hi[1] = (__nv_bfloat162*)Xk_h; a1.lo[1] = (__nv_bfloat162*)Xk_l;
        a1.src[2] = (const float4*)value; a1.hi[2] = (__nv_bfloat162*)Xv_h; a1.lo[2] = (__nv_bfloat162*)Xv_l;
        a1.src[3] = (const float4*)Wq;    a1.hi[3] = (__nv_bfloat162*)Wq_h; a1.lo[3] = (__nv_bfloat162*)Wq_l;
        split_multi<<<dim3(sg, 4), 256>>>(a1, n4);
        SplitArgs a2;
        a2.src[0] = (const float4*)Wk;    a2.hi[0] = (__nv_bfloat162*)Wk_h; a2.lo[0] = (__nv_bfloat162*)Wk_l;
        a2.src[1] = (const float4*)Wv;    a2.hi[1] = (__nv_bfloat162*)Wv_h; a2.lo[1] = (__nv_bfloat162*)Wv_l;
        a2.src[2] = (const float4*)Wo;    a2.hi[2] = (__nv_bfloat162*)Wo_h; a2.lo[2] = (__nv_bfloat162*)Wo_l;
        a2.src[3] = (const float4*)Wq;    a2.hi[3] = (__nv_bfloat162*)Wq_h; a2.lo[3] = (__nv_bfloat162*)Wq_l; // unused lane guard
        split_multi<<<dim3(sg, 3), 256>>>(a2, n4);
    }

    dim3 blk(GT);
    dim3 gP(DMODEL / BN, MTOT / BM, 1);            // 64 x 32

    // L3: Q   L4: K   L5: scores   L6: V (<- ncu capture slot)   L7: softmax   L8: out
    gemm_bf16x3<<<gP, blk, SMEM_REQ>>>(Xq_h, Xq_l, Wq_h, Wq_l,
        nullptr, Qh, Ql, bq, 1.f, DMODEL, DMODEL, 0, 0, 0);
    gemm_bf16x3<<<gP, blk, SMEM_REQ>>>(Xk_h, Xk_l, Wk_h, Wk_l,
        nullptr, Kh, Kl, bk, 1.f, DMODEL, DMODEL, 0, 0, 0);
    {
        dim3 gS(SEQ / BN, SEQ / BM, NBATCH);       // 8 x 4 x 64
        long long sbz = (long long)SEQ * SEQ;
        gemm_bf16x3<<<gS, blk, SMEM_REQ>>>(Qh, Ql, Kh, Kl,
            Sf, nullptr, nullptr, nullptr, rsqrtf((float)HDIM),
            HDIM, SEQ, sbz, sbz, sbz);
    }
    gemm_bf16x3<<<gP, blk, SMEM_REQ>>>(Xv_h, Xv_l, Wv_h, Wv_l,
        Vf, nullptr, nullptr, bv, 1.f, DMODEL, DMODEL, 0, 0, 0);

    softmax_mul_scatter<<<(NBATCH * SEQ) / 256, 256>>>(Sf, Vf, Yh, Yl);

    gemm_bf16x3<<<gP, blk, SMEM_REQ>>>(Yh, Yl, Wo_h, Wo_l,
        out, nullptr, nullptr, bo, 1.f, DMODEL, DMODEL, 0, 0, 0);
}